// round 14
// baseline (speedup 1.0000x reference)
#include <cuda_runtime.h>
#include <cuda_bf16.h>
#include <stdint.h>
#include <math.h>

#define Bc 256
#define Tc 512
#define Dc 256
#define Hc 256
#define Ac 128
#define ZC 1024
#define Vc 50000

#define NCTA_L 128

// ---------------- scratch globals --------------------------------------------
__device__ __nv_bfloat16 g_xzh[(size_t)Bc * Tc * ZC];  // xz bf16 hi
__device__ __nv_bfloat16 g_xzl[(size_t)Bc * Tc * ZC];  // xz bf16 lo
__device__ __nv_bfloat16 g_ohi[(size_t)Bc * Tc * Hc];  // outs, bf16 hi
__device__ __nv_bfloat16 g_olo[(size_t)Bc * Tc * Hc];  // outs, bf16 lo
__device__ float g_vu[Bc * Tc];
__device__ int   g_seqlen[Bc];
__device__ __nv_bfloat16 g_hhi[2][Bc][Hc];
__device__ __nv_bfloat16 g_hlo[2][Bc][Hc];
__device__ unsigned g_bar[16 * 32];
__device__ __nv_bfloat16 g_Bhi[1024 * 256];   // W_x^T hi, [n][k]
__device__ __nv_bfloat16 g_Blo[1024 * 256];
__device__ __nv_bfloat16 g_Whhi[1024 * 256];  // W_h^T hi, [n][k]
__device__ __nv_bfloat16 g_Whlo[1024 * 256];
__device__ __nv_bfloat16 g_WOhi[128 * 256];   // w_omega^T hi, [a][k]
__device__ __nv_bfloat16 g_WOlo[128 * 256];
__device__ __nv_bfloat16 g_Ehi[(size_t)Vc * 256];
__device__ __nv_bfloat16 g_Elo[(size_t)Vc * 256];

typedef unsigned long long u64;

__device__ __forceinline__ float sigm(float x) { return 1.0f / (1.0f + __expf(-x)); }
__device__ __forceinline__ float tanh_f(float x) {
    float ax = fabsf(x);
    float e = __expf(-2.0f * ax);
    float r = (1.0f - e) / (1.0f + e);
    return copysignf(r, x);
}
__device__ __forceinline__ uint32_t smem_u32(const void* p) {
    uint32_t a;
    asm("{ .reg .u64 t; cvta.to.shared.u64 t, %1; cvt.u32.u64 %0, t; }"
        : "=r"(a) : "l"(p));
    return a;
}
__device__ __forceinline__ uint32_t pack_bf2(float a, float b) {
    __nv_bfloat162 h = __floats2bfloat162_rn(a, b);
    return *(uint32_t*)&h;
}

// ---------------- mma.sync / cp.async helpers ----------------------------------
__device__ __forceinline__ void ldmx4(uint32_t* r, uint32_t addr) {
    asm volatile("ldmatrix.sync.aligned.m8n8.x4.shared.b16 {%0,%1,%2,%3}, [%4];"
                 : "=r"(r[0]), "=r"(r[1]), "=r"(r[2]), "=r"(r[3]) : "r"(addr));
}
__device__ __forceinline__ void mma16816(float* c, const uint32_t* a,
                                         uint32_t b0, uint32_t b1) {
    asm volatile(
        "mma.sync.aligned.m16n8k16.row.col.f32.bf16.bf16.f32 "
        "{%0,%1,%2,%3}, {%4,%5,%6,%7}, {%8,%9}, {%0,%1,%2,%3};"
        : "+f"(c[0]), "+f"(c[1]), "+f"(c[2]), "+f"(c[3])
        : "r"(a[0]), "r"(a[1]), "r"(a[2]), "r"(a[3]), "r"(b0), "r"(b1));
}
#define CP16(dst, src) \
    asm volatile("cp.async.cg.shared.global [%0], [%1], 16;" \
                 :: "r"(dst), "l"(src) : "memory")
#define CP_COMMIT() asm volatile("cp.async.commit_group;" ::: "memory")
#define CP_WAIT0()  asm volatile("cp.async.wait_group 0;" ::: "memory")

// ---------------- K0: seq_len --------------------------------------------------
__global__ void k_seqlen(const int* __restrict__ x) {
    const int b = blockIdx.x;
    const int tid = threadIdx.x;
    int c = (x[b * Tc + tid] != 0) + (x[b * Tc + 256 + tid] != 0);
    #pragma unroll
    for (int o = 16; o; o >>= 1) c += __shfl_xor_sync(~0u, c, o);
    __shared__ int s[8];
    if ((tid & 31) == 0) s[tid >> 5] = c;
    __syncthreads();
    if (tid == 0) {
        int t = 0;
        #pragma unroll
        for (int i = 0; i < 8; i++) t += s[i];
        g_seqlen[b] = t;
    }
}

__global__ void k_init() {
    if (threadIdx.x < 16 * 32) g_bar[threadIdx.x] = 0u;
}

// ---------------- K0b: W transpose + bf16 hi/lo split --------------------------
__global__ void k_wsplit(const float* __restrict__ lk, int koff, int which) {
    __shared__ float s[32][33];
    const int kt = blockIdx.x * 32;
    const int nt = blockIdx.y * 32;
    const int tx = threadIdx.x;
    const int ty = threadIdx.y;
    #pragma unroll
    for (int i = 0; i < 4; i++) {
        s[ty + 8 * i][tx] = lk[(size_t)(koff + kt + ty + 8 * i) * ZC + nt + tx];
    }
    __syncthreads();
    __nv_bfloat16* dhi = which ? g_Whhi : g_Bhi;
    __nv_bfloat16* dlo = which ? g_Whlo : g_Blo;
    #pragma unroll
    for (int i = 0; i < 4; i++) {
        const int n = ty + 8 * i;
        float v = s[tx][n];
        __nv_bfloat16 h = __float2bfloat16(v);
        float lo = v - __bfloat162float(h);
        dhi[(size_t)(nt + n) * 256 + kt + tx] = h;
        dlo[(size_t)(nt + n) * 256 + kt + tx] = __float2bfloat16(lo);
    }
}

// ---------------- K0b2: w_omega transpose + split -------------------------------
__global__ void k_wosplit(const float* __restrict__ w_om) {
    __shared__ float s[32][33];
    const int kt = blockIdx.x * 32;
    const int at = blockIdx.y * 32;
    const int tx = threadIdx.x;
    const int ty = threadIdx.y;
    #pragma unroll
    for (int i = 0; i < 4; i++) {
        s[ty + 8 * i][tx] = w_om[(size_t)(kt + ty + 8 * i) * Ac + at + tx];
    }
    __syncthreads();
    #pragma unroll
    for (int i = 0; i < 4; i++) {
        const int n = ty + 8 * i;
        float v = s[tx][n];
        __nv_bfloat16 h = __float2bfloat16(v);
        float lo = v - __bfloat162float(h);
        g_WOhi[(size_t)(at + n) * 256 + kt + tx] = h;
        g_WOlo[(size_t)(at + n) * 256 + kt + tx] = __float2bfloat16(lo);
    }
}

// ---------------- K0c: embedding table bf16 hi/lo split ------------------------
__global__ __launch_bounds__(256)
void k_esplit(const float* __restrict__ embed) {
    const size_t base = ((size_t)blockIdx.x * 256 + threadIdx.x) * 8;
    if (base >= (size_t)Vc * 256) return;
    float4 v0 = *(const float4*)(embed + base);
    float4 v1 = *(const float4*)(embed + base + 4);
    __nv_bfloat162 h0 = __floats2bfloat162_rn(v0.x, v0.y);
    __nv_bfloat162 h1 = __floats2bfloat162_rn(v0.z, v0.w);
    __nv_bfloat162 h2 = __floats2bfloat162_rn(v1.x, v1.y);
    __nv_bfloat162 h3 = __floats2bfloat162_rn(v1.z, v1.w);
    __nv_bfloat162 l0 = __floats2bfloat162_rn(v0.x - __bfloat162float(h0.x),
                                              v0.y - __bfloat162float(h0.y));
    __nv_bfloat162 l1 = __floats2bfloat162_rn(v0.z - __bfloat162float(h1.x),
                                              v0.w - __bfloat162float(h1.y));
    __nv_bfloat162 l2 = __floats2bfloat162_rn(v1.x - __bfloat162float(h2.x),
                                              v1.y - __bfloat162float(h2.y));
    __nv_bfloat162 l3 = __floats2bfloat162_rn(v1.z - __bfloat162float(h3.x),
                                              v1.w - __bfloat162float(h3.y));
    uint4 ph;
    ph.x = *(uint32_t*)&h0; ph.y = *(uint32_t*)&h1;
    ph.z = *(uint32_t*)&h2; ph.w = *(uint32_t*)&h3;
    uint4 pl;
    pl.x = *(uint32_t*)&l0; pl.y = *(uint32_t*)&l1;
    pl.z = *(uint32_t*)&l2; pl.w = *(uint32_t*)&l3;
    __stcs((uint4*)&g_Ehi[base], ph);
    __stcs((uint4*)&g_Elo[base], pl);
}

// ---------------- shared GEMM pipeline constants -------------------------------
#define AST2 40
#define X_TOK  0
#define X_BIAS 512
#define X_ARR  10240
#define X_STG  (4 * X_ARR)
#define X_BASE 1024
#define SMX_TOTAL (X_BASE + 2 * X_STG)      // 82944

#define VU_BASE 4096
#define SMV_TOTAL (VU_BASE + 2 * X_STG)     // 86016

extern __shared__ char smx[];

// ---------------- K1: xz GEMM, single-sync cp.async pipeline -------------------
__global__ __launch_bounds__(256, 2)
void k_xgemm4(const int* __restrict__ x, const float* __restrict__ bias) {
    const uint32_t sb = smem_u32(smx);
    const int tid  = threadIdx.x;
    const int wid  = tid >> 5;
    const int lane = tid & 31;
    const int bn = blockIdx.x * 128;
    const int bm = blockIdx.y * 128;

    int*   stok  = (int*)(smx + X_TOK);
    float* sbias = (float*)(smx + X_BIAS);

    if (tid < 128) {
        stok[tid]  = x[bm + tid];
        sbias[tid] = bias[bn + tid];
    }
    __syncthreads();

    const int wm = (wid & 1) * 64;
    const int wn = (wid >> 1) * 32;

    float acc[4][4][4];
    #pragma unroll
    for (int mt = 0; mt < 4; mt++)
        #pragma unroll
        for (int nt = 0; nt < 4; nt++)
            #pragma unroll
            for (int i = 0; i < 4; i++) acc[mt][nt][i] = 0.f;

    const int lrow = tid >> 1;
    const int lk16 = (tid & 1) * 16;
    const size_t asrc = (size_t)stok[lrow] * 256 + lk16;
    const size_t bsrc = (size_t)(bn + lrow) * 256 + lk16;
    const uint32_t ldst = (uint32_t)((lrow * AST2 + lk16) * 2);

    const uint32_t a_comp = (uint32_t)(((wm + (lane & 15)) * AST2 + (lane >> 4) * 8) * 2);
    const uint32_t b_comp = (uint32_t)(((wn + ((lane >> 4) & 1) * 8 + (lane & 7)) * AST2
                                        + ((lane >> 3) & 1) * 8) * 2);

#define X4_ISSUE(CK, STG) do {                                                 \
    const int _kb = (CK) * 32;                                                 \
    const uint32_t _st = sb + X_BASE + (STG) * X_STG + ldst;                   \
    CP16(_st,                 (const char*)&g_Ehi[asrc + _kb]);                \
    CP16(_st + 16,            (const char*)&g_Ehi[asrc + _kb + 8]);            \
    CP16(_st + X_ARR,         (const char*)&g_Elo[asrc + _kb]);                \
    CP16(_st + X_ARR + 16,    (const char*)&g_Elo[asrc + _kb + 8]);            \
    CP16(_st + 2*X_ARR,       (const char*)&g_Bhi[bsrc + _kb]);                \
    CP16(_st + 2*X_ARR + 16,  (const char*)&g_Bhi[bsrc + _kb + 8]);            \
    CP16(_st + 3*X_ARR,       (const char*)&g_Blo[bsrc + _kb]);                \
    CP16(_st + 3*X_ARR + 16,  (const char*)&g_Blo[bsrc + _kb + 8]);            \
    CP_COMMIT();                                                               \
} while (0)

    X4_ISSUE(0, 0);

    for (int ck = 0; ck < 8; ck++) {
        CP_WAIT0();
        __syncthreads();
        // issue next chunk AFTER the sync: its target stage was last read in
        // MMA(ck-1), which every thread finished before reaching this sync.
        if (ck < 7) X4_ISSUE(ck + 1, (ck + 1) & 1);

        const uint32_t stg = sb + X_BASE + (uint32_t)((ck & 1) * X_STG);
        const uint32_t aoff_hi = stg + a_comp;
        const uint32_t aoff_lo = stg + X_ARR + a_comp;
        const uint32_t boff_hi = stg + 2 * X_ARR + b_comp;
        const uint32_t boff_lo = stg + 3 * X_ARR + b_comp;

        #pragma unroll
        for (int ks = 0; ks < 2; ks++) {
            const uint32_t kb = (uint32_t)(ks * 32);
            uint32_t bhi[2][4];
            uint32_t blo[2][4];
            #pragma unroll
            for (int np = 0; np < 2; np++) {
                const uint32_t pb = (uint32_t)(np * 16 * AST2 * 2) + kb;
                ldmx4(bhi[np], boff_hi + pb);
                ldmx4(blo[np], boff_lo + pb);
            }
            #pragma unroll
            for (int mt = 0; mt < 4; mt++) {
                const uint32_t mb = (uint32_t)(mt * 16 * AST2 * 2) + kb;
                uint32_t ahi[4];
                uint32_t alo[4];
                ldmx4(ahi, aoff_hi + mb);
                ldmx4(alo, aoff_lo + mb);
                #pragma unroll
                for (int nt = 0; nt < 4; nt++) {
                    const uint32_t b0 = bhi[nt >> 1][(nt & 1) * 2];
                    const uint32_t b1 = bhi[nt >> 1][(nt & 1) * 2 + 1];
                    const uint32_t c0 = blo[nt >> 1][(nt & 1) * 2];
                    const uint32_t c1 = blo[nt >> 1][(nt & 1) * 2 + 1];
                    mma16816(acc[mt][nt], ahi, b0, b1);
                    mma16816(acc[mt][nt], alo, b0, b1);
                    mma16816(acc[mt][nt], ahi, c0, c1);
                }
            }
        }
    }

    // ---- epilogue: + bias, bf16 hi/lo split stores ----
    #pragma unroll
    for (int mt = 0; mt < 4; mt++) {
        const int m0 = bm + wm + mt * 16 + (lane >> 2);
        #pragma unroll
        for (int nt = 0; nt < 4; nt++) {
            const int nl = wn + nt * 8 + (lane & 3) * 2;
            const float b0 = sbias[nl];
            const float b1 = sbias[nl + 1];
            float v00 = acc[mt][nt][0] + b0;
            float v01 = acc[mt][nt][1] + b1;
            float v10 = acc[mt][nt][2] + b0;
            float v11 = acc[mt][nt][3] + b1;
            __nv_bfloat162 h0 = __floats2bfloat162_rn(v00, v01);
            __nv_bfloat162 h1 = __floats2bfloat162_rn(v10, v11);
            uint32_t l0 = pack_bf2(v00 - __bfloat162float(h0.x),
                                   v01 - __bfloat162float(h0.y));
            uint32_t l1 = pack_bf2(v10 - __bfloat162float(h1.x),
                                   v11 - __bfloat162float(h1.y));
            const size_t o0 = (size_t)m0 * ZC + bn + nl;
            const size_t o1 = (size_t)(m0 + 8) * ZC + bn + nl;
            __stcs((uint32_t*)&g_xzh[o0], *(uint32_t*)&h0);
            __stcs((uint32_t*)&g_xzh[o1], *(uint32_t*)&h1);
            __stcs((uint32_t*)&g_xzl[o0], l0);
            __stcs((uint32_t*)&g_xzl[o1], l1);
        }
    }
}

// ---------------- K2: LSTM (R13-passing, xz reads -> bf16 hi/lo) ---------------
#define WST 264
#define ZST 136
#define L4_WHI 0
#define L4_WLO 67584
#define L4_HHI 135168
#define L4_HLO 143616
#define L4_ZP  152064
#define SMEM_L4 221696

__global__ __launch_bounds__(512, 1)
void k_lstm5() {
    extern __shared__ char sml[];
    __nv_bfloat16* sWhi = (__nv_bfloat16*)(sml + L4_WHI);
    __nv_bfloat16* sWlo = (__nv_bfloat16*)(sml + L4_WLO);
    __nv_bfloat16* sHhi = (__nv_bfloat16*)(sml + L4_HHI);
    __nv_bfloat16* sHlo = (__nv_bfloat16*)(sml + L4_HLO);
    float* sZp = (float*)(sml + L4_ZP);
    const uint32_t sbase = smem_u32(sml);

    const int tid = threadIdx.x;
    const int g  = blockIdx.x & 7;
    const int bg = blockIdx.x >> 3;
    const int u0 = g * 32;
    const int b0 = bg * 16;
    unsigned* const ctr = &g_bar[bg * 32];

    {
        const int n = tid >> 2;
        const int c = tid & 3;
        const int gcol = (n >> 5) * 256 + u0 + (n & 31);
        const size_t src = (size_t)gcol * 256 + c * 64;
        const int dst = n * WST + c * 64;
        #pragma unroll
        for (int i = 0; i < 8; i++) {
            *(uint4*)&sWhi[dst + i * 8] = *(const uint4*)&g_Whhi[src + i * 8];
            *(uint4*)&sWlo[dst + i * 8] = *(const uint4*)&g_Whlo[src + i * 8];
        }
    }

    const int wid  = tid >> 5;
    const int lane = tid & 31;
    const int nh = wid & 1;
    const int kg = wid >> 1;
    const int n0 = nh * 64;
    const int k0 = kg * 32;

    const uint32_t a_part = (uint32_t)((lane & 15) * WST + (lane >> 4) * 8) * 2;
    const uint32_t aoff_hi = sbase + L4_HHI + a_part;
    const uint32_t aoff_lo = sbase + L4_HLO + a_part;
    const uint32_t brow = (uint32_t)(n0 + ((lane >> 4) & 1) * 8 + (lane & 7));
    const uint32_t bk   = (uint32_t)(((lane >> 3) & 1) * 8);
    const uint32_t b_part = (brow * WST + bk) * 2;
    const uint32_t boff_hi = sbase + L4_WHI + b_part;
    const uint32_t boff_lo = sbase + L4_WLO + b_part;

    const int gu = lane;
    const int gb = wid;
    float c_reg = 0.f;
    float h_reg = 0.f;
    const int slen = g_seqlen[b0 + gb];
    const size_t xzg = ((size_t)(b0 + gb) * Tc) * ZC + u0 + gu;
    const size_t og  = ((size_t)(b0 + gb) * Tc) * Hc + u0 + gu;
    __nv_bfloat16* const ghh0 = &g_hhi[0][b0 + gb][u0 + gu];
    __nv_bfloat16* const ghh1 = &g_hhi[1][b0 + gb][u0 + gu];
    __nv_bfloat16* const ghl0 = &g_hlo[0][b0 + gb][u0 + gu];
    __nv_bfloat16* const ghl1 = &g_hlo[1][b0 + gb][u0 + gu];

    const int srow = tid >> 5;
    const int skof = lane * 8;
    const __nv_bfloat16* const hshi0 = &g_hhi[0][b0 + srow][skof];
    const __nv_bfloat16* const hshi1 = &g_hhi[1][b0 + srow][skof];
    const __nv_bfloat16* const hslo0 = &g_hlo[0][b0 + srow][skof];
    const __nv_bfloat16* const hslo1 = &g_hlo[1][b0 + srow][skof];
    const int hdst = srow * WST + skof;

    // prefetch xz for t=0 (bf16 hi + lo)
    float xg0, xg1, xg2, xg3;
    {
        xg0 = __bfloat162float(__ldcs(&g_xzh[xzg]))       + __bfloat162float(__ldcs(&g_xzl[xzg]));
        xg1 = __bfloat162float(__ldcs(&g_xzh[xzg + 256])) + __bfloat162float(__ldcs(&g_xzl[xzg + 256]));
        xg2 = __bfloat162float(__ldcs(&g_xzh[xzg + 512])) + __bfloat162float(__ldcs(&g_xzl[xzg + 512]));
        xg3 = __bfloat162float(__ldcs(&g_xzh[xzg + 768])) + __bfloat162float(__ldcs(&g_xzl[xzg + 768]));
    }

    for (int t = 0; t < Tc; t++) {
        if (t == 0) {
            uint4 z4 = make_uint4(0u, 0u, 0u, 0u);
            *(uint4*)&sHhi[hdst] = z4;
            *(uint4*)&sHlo[hdst] = z4;
        } else {
            const int bsel = t & 1;
            uint4 vh = __ldcg((const uint4*)(bsel ? hshi1 : hshi0));
            uint4 vl = __ldcg((const uint4*)(bsel ? hslo1 : hslo0));
            *(uint4*)&sHhi[hdst] = vh;
            *(uint4*)&sHlo[hdst] = vl;
        }
        __syncthreads();

        float acc[8][4];
        #pragma unroll
        for (int nt = 0; nt < 8; nt++)
            #pragma unroll
            for (int i = 0; i < 4; i++) acc[nt][i] = 0.f;

        #pragma unroll
        for (int ks = 0; ks < 2; ks++) {
            const uint32_t kb = (uint32_t)((k0 + ks * 16) * 2);
            uint32_t ahi[4], alo[4];
            ldmx4(ahi, aoff_hi + kb);
            ldmx4(alo, aoff_lo + kb);
            #pragma unroll
            for (int p = 0; p < 4; p++) {
                const uint32_t pb = (uint32_t)(p * 16 * WST * 2) + kb;
                uint32_t bhi[4], blo[4];
                ldmx4(bhi, boff_hi + pb);
                ldmx4(blo, boff_lo + pb);
                mma16816(acc[2 * p],     ahi, bhi[0], bhi[1]);
                mma16816(acc[2 * p + 1], ahi, bhi[2], bhi[3]);
                mma16816(acc[2 * p],     alo, bhi[0], bhi[1]);
                mma16816(acc[2 * p + 1], alo, bhi[2], bhi[3]);
                mma16816(acc[2 * p],     ahi, blo[0], blo[1]);
                mma16816(acc[2 * p + 1], ahi, blo[2], blo[3]);
            }
        }

        {
            const int m  = lane >> 2;
            const int cb = (lane & 3) * 2;
            #pragma unroll
            for (int nt = 0; nt < 8; nt++) {
                const int col = n0 + nt * 8 + cb;
                *(float2*)&sZp[(kg * 16 + m) * ZST + col] =
                    make_float2(acc[nt][0], acc[nt][1]);
                *(float2*)&sZp[(kg * 16 + m + 8) * ZST + col] =
                    make_float2(acc[nt][2], acc[nt][3]);
            }
        }
        __syncthreads();

        float zi = xg0;
        float zj = xg1;
        float zf = xg2;
        float zo = xg3;
        #pragma unroll
        for (int p = 0; p < 8; p++) {
            const float* zp = &sZp[(p * 16 + gb) * ZST];
            zi += zp[gu];
            zj += zp[32 + gu];
            zf += zp[64 + gu];
            zo += zp[96 + gu];
        }
        float cn = c_reg * sigm(zf + 1.f) + sigm(zi) * tanh_f(zj);
        float hn = tanh_f(cn) * sigm(zo);
        bool m = (t < slen);
        c_reg = m ? cn : c_reg;
        h_reg = m ? hn : h_reg;

        {
            __nv_bfloat16 hh = __float2bfloat16(h_reg);
            __nv_bfloat16 hl = __float2bfloat16(h_reg - __bfloat162float(hh));
            const int nb = (t + 1) & 1;
            *(nb ? ghh1 : ghh0) = hh;
            *(nb ? ghl1 : ghl0) = hl;
        }

        __threadfence();
        __syncthreads();
        if (tid == 0) atomicAdd(ctr, 1u);

        // hidden under barrier skew: outs store + next xz prefetch
        {
            float o = m ? hn : 0.f;
            __nv_bfloat16 oh = __float2bfloat16(o);
            __nv_bfloat16 ol = __float2bfloat16(o - __bfloat162float(oh));
            g_ohi[og + (size_t)t * Hc] = oh;
            g_olo[og + (size_t)t * Hc] = ol;
        }
        if (t + 1 < Tc) {
            const size_t xb = xzg + (size_t)(t + 1) * ZC;
            xg0 = __bfloat162float(__ldcs(&g_xzh[xb]))       + __bfloat162float(__ldcs(&g_xzl[xb]));
            xg1 = __bfloat162float(__ldcs(&g_xzh[xb + 256])) + __bfloat162float(__ldcs(&g_xzl[xb + 256]));
            xg2 = __bfloat162float(__ldcs(&g_xzh[xb + 512])) + __bfloat162float(__ldcs(&g_xzl[xb + 512]));
            xg3 = __bfloat162float(__ldcs(&g_xzh[xb + 768])) + __bfloat162float(__ldcs(&g_xzl[xb + 768]));
        }

        if (tid == 0) {
            const unsigned target = (unsigned)(t + 1) * 8u;
            unsigned v;
            do {
                asm volatile("ld.global.acquire.gpu.u32 %0, [%1];"
                             : "=r"(v) : "l"(ctr) : "memory");
            } while (v < target);
        }
        __syncthreads();
    }
}

// ---------------- K3: attention scores via HMMA, single-sync pipeline ----------
__global__ __launch_bounds__(256, 2)
void k_vu2(const float* __restrict__ b_om, const float* __restrict__ u_om) {
    const uint32_t sb = smem_u32(smx);
    const int tid  = threadIdx.x;
    const int wid  = tid >> 5;
    const int lane = tid & 31;
    const int bm = blockIdx.x * 128;

    float* sbom = (float*)(smx + 0);
    float* suom = (float*)(smx + 512);
    float* sred = (float*)(smx + 1024);

    if (tid < 128) {
        sbom[tid] = b_om[tid];
        suom[tid] = u_om[tid];
    }
    __syncthreads();

    const int wm = (wid & 1) * 64;
    const int wn = (wid >> 1) * 32;

    float acc[4][4][4];
    #pragma unroll
    for (int mt = 0; mt < 4; mt++)
        #pragma unroll
        for (int nt = 0; nt < 4; nt++)
            #pragma unroll
            for (int i = 0; i < 4; i++) acc[mt][nt][i] = 0.f;

    const int lrow = tid >> 1;
    const int lk16 = (tid & 1) * 16;
    const size_t asrc = (size_t)(bm + lrow) * 256 + lk16;
    const size_t bsrc = (size_t)lrow * 256 + lk16;
    const uint32_t ldst = (uint32_t)((lrow * AST2 + lk16) * 2);

    const uint32_t a_comp = (uint32_t)(((wm + (lane & 15)) * AST2 + (lane >> 4) * 8) * 2);
    const uint32_t b_comp = (uint32_t)(((wn + ((lane >> 4) & 1) * 8 + (lane & 7)) * AST2
                                        + ((lane >> 3) & 1) * 8) * 2);

#define VU_ISSUE(CK, STG) do {                                                 \
    const int _kb = (CK) * 32;                                                 \
    const uint32_t _st = sb + VU_BASE + (STG) * X_STG + ldst;                  \
    CP16(_st,                 (const char*)&g_ohi[asrc + _kb]);                \
    CP16(_st + 16,            (const char*)&g_ohi[asrc + _kb + 8]);            \
    CP16(_st + X_ARR,         (const char*)&g_olo[asrc + _kb]);                \
    CP16(_st + X_ARR + 16,    (const char*)&g_olo[asrc + _kb + 8]);            \
    CP16(_st + 2*X_ARR,       (const char*)&g_WOhi[bsrc + _kb]);               \
    CP16(_st + 2*X_ARR + 16,  (const char*)&g_WOhi[bsrc + _kb + 8]);           \
    CP16(_st + 3*X_ARR,       (const char*)&g_WOlo[bsrc + _kb]);               \
    CP16(_st + 3*X_ARR + 16,  (const char*)&g_WOlo[bsrc + _kb + 8]);           \
    CP_COMMIT();                                                               \
} while (0)

    VU_ISSUE(0, 0);

    for (int ck = 0; ck < 8; ck++) {
        CP_WAIT0();
        __syncthreads();
        if (ck < 7) VU_ISSUE(ck + 1, (ck + 1) & 1);

        const uint32_t stg = sb + VU_BASE + (uint32_t)((ck & 1) * X_STG);
        const uint32_t aoff_hi = stg + a_comp;
        const uint32_t aoff_lo = stg + X_ARR + a_comp;
        const uint32_t boff_hi = stg + 2 * X_ARR + b_comp;
        const uint32_t boff_lo = stg + 3 * X_ARR + b_comp;

        #pragma unroll
        for (int ks = 0; ks < 2; ks++) {
            const uint32_t kb = (uint32_t)(ks * 32);
            uint32_t bhi[2][4];
            uint32_t blo[2][4];
            #pragma unroll
            for (int np = 0; np < 2; np++) {
                const uint32_t pb = (uint32_t)(np * 16 * AST2 * 2) + kb;
                ldmx4(bhi[np], boff_hi + pb);
                ldmx4(blo[np], boff_lo + pb);
            }
            #pragma unroll
            for (int mt = 0; mt < 4; mt++) {
                const uint32_t mb = (uint32_t)(mt * 16 * AST2 * 2) + kb;
                uint32_t ahi[4];
                uint32_t alo[4];
                ldmx4(ahi, aoff_hi + mb);
                ldmx4(alo, aoff_lo + mb);
                #pragma unroll
                for (int nt = 0; nt < 4; nt++) {
                    const uint32_t b0 = bhi[nt >> 1][(nt & 1) * 2];
                    const uint32_t b1 = bhi[nt >> 1][(nt & 1) * 2 + 1];
                    const uint32_t c0 = blo[nt >> 1][(nt & 1) * 2];
                    const uint32_t c1 = blo[nt >> 1][(nt & 1) * 2 + 1];
                    mma16816(acc[mt][nt], ahi, b0, b1);
                    mma16816(acc[mt][nt], alo, b0, b1);
                    mma16816(acc[mt][nt], ahi, c0, c1);
                }
            }
        }
    }
    __syncthreads();

    // ---- epilogue: tanh(+b)*u, row-sum over n=128 ----
    #pragma unroll
    for (int mt = 0; mt < 4; mt++) {
        float rsum[2];
        rsum[0] = 0.f;
        rsum[1] = 0.f;
        #pragma unroll
        for (int nt = 0; nt < 4; nt++) {
            #pragma unroll
            for (int i = 0; i < 4; i++) {
                const int col = wn + nt * 8 + (lane & 3) * 2 + (i & 1);
                float v = tanh_f(acc[mt][nt][i] + sbom[col]) * suom[col];
                rsum[i >> 1] += v;
            }
        }
        #pragma unroll
        for (int hf = 0; hf < 2; hf++) {
            float r = rsum[hf];
            r += __shfl_xor_sync(~0u, r, 1);
            r += __shfl_xor_sync(~0u, r, 2);
            if ((lane & 3) == 0) {
                const int row = wm + mt * 16 + (lane >> 2) + hf * 8;
                sred[row * 4 + (wid >> 1)] = r;
            }
        }
    }
    __syncthreads();
    if (tid < 128) {
        g_vu[bm + tid] = sred[tid * 4] + sred[tid * 4 + 1]
                       + sred[tid * 4 + 2] + sred[tid * 4 + 3];
    }
}

// ---------------- block reductions ----------------------------------------------
__device__ __forceinline__ float blk_sum(float v, float* sr, int tid) {
    #pragma unroll
    for (int o = 16; o; o >>= 1) v += __shfl_xor_sync(~0u, v, o);
    if ((tid & 31) == 0) sr[tid >> 5] = v;
    __syncthreads();
    if (tid < 32) {
        float xx = (tid < 8) ? sr[tid] : 0.f;
        #pragma unroll
        for (int o = 4; o; o >>= 1) xx += __shfl_xor_sync(~0u, xx, o);
        if (tid == 0) sr[0] = xx;
    }
    __syncthreads();
    float r = sr[0];
    __syncthreads();
    return r;
}
__device__ __forceinline__ float blk_max(float v, float* sr, int tid) {
    #pragma unroll
    for (int o = 16; o; o >>= 1) v = fmaxf(v, __shfl_xor_sync(~0u, v, o));
    if ((tid & 31) == 0) sr[tid >> 5] = v;
    __syncthreads();
    if (tid < 32) {
        float xx = (tid < 8) ? sr[tid] : -INFINITY;
        #pragma unroll
        for (int o = 4; o; o >>= 1) xx = fmaxf(xx, __shfl_xor_sync(~0u, xx, o));
        if (tid == 0) sr[0] = xx;
    }
    __syncthreads();
    float r = sr[0];
    __syncthreads();
    return r;
}

// ---------------- K4: softmax over T, weighted sum, head ------------------------
__global__ __launch_bounds__(256)
void k_final(const float* __restrict__ w2, const float* __restrict__ b2,
             float* __restrict__ out) {
    __shared__ float sa[Tc];
    __shared__ float sr[32];

    const int b = blockIdx.x;
    const int tid = threadIdx.x;
    const float v0 = g_vu[b * Tc + tid];
    const float v1 = g_vu[b * Tc + 256 + tid];

    const float m = blk_max(fmaxf(v0, v1), sr, tid);
    const float e0 = expf(v0 - m);
    const float e1 = expf(v1 - m);
    sa[tid] = e0;
    sa[tid + 256] = e1;
    const float Z = blk_sum(e0 + e1, sr, tid);
    const float Zinv = 1.0f / Z;

    const __nv_bfloat16* oph = g_ohi + (size_t)b * Tc * Hc + tid;
    const __nv_bfloat16* opl = g_olo + (size_t)b * Tc * Hc + tid;
    float a[8];
    #pragma unroll
    for (int i = 0; i < 8; i++) a[i] = 0.f;
    for (int t = 0; t < Tc; t += 8) {
        #pragma unroll
        for (int i = 0; i < 8; i++) {
            const size_t off = (size_t)(t + i) * Hc;
            float v = __bfloat162float(__ldcg(&oph[off]))
                    + __bfloat162float(__ldcg(&opl[off]));
            a[i] = fmaf(v, sa[t + i], a[i]);
        }
    }
    float acc = (((a[0] + a[1]) + (a[2] + a[3])) +
                 ((a[4] + a[5]) + (a[6] + a[7]))) * Zinv;

    const float l0 = blk_sum(acc * w2[tid * 2], sr, tid);
    const float l1 = blk_sum(acc * w2[tid * 2 + 1], sr, tid);

    if (tid == 0) {
        float aa0 = l0 + b2[0];
        float aa1 = l1 + b2[1];
        float mm = fmaxf(aa0, aa1);
        float x0 = expf(aa0 - mm);
        float x1 = expf(aa1 - mm);
        float s = 1.0f / (x0 + x1);
        out[b * 2 + 0] = x0 * s;
        out[b * 2 + 1] = x1 * s;
    }
}

// ---------------- launcher -------------------------------------------------------
extern "C" void kernel_launch(void* const* d_in, const int* in_sizes, int n_in,
                              void* d_out, int out_size) {
    const int*   x     = (const int*)  d_in[0];
    const float* embed = (const float*)d_in[1];
    const float* lk    = (const float*)d_in[2];
    const float* bias  = (const float*)d_in[3];
    const float* w_om  = (const float*)d_in[4];
    const float* b_om  = (const float*)d_in[5];
    const float* u_om  = (const float*)d_in[6];
    const float* w2    = (const float*)d_in[7];
    const float* b2    = (const float*)d_in[8];
    float* out = (float*)d_out;

    cudaFuncSetAttribute(k_xgemm4, cudaFuncAttributeMaxDynamicSharedMemorySize,
                         SMX_TOTAL);
    cudaFuncSetAttribute(k_vu2, cudaFuncAttributeMaxDynamicSharedMemorySize,
                         SMV_TOTAL);
    cudaFuncSetAttribute(k_lstm5, cudaFuncAttributeMaxDynamicSharedMemorySize,
                         SMEM_L4);

    k_seqlen<<<Bc, 256>>>(x);
    k_init<<<1, 512>>>();

    dim3 gw(8, 32);
    dim3 bw(32, 8);
    k_wsplit<<<gw, bw>>>(lk, 0, 0);     // W_x
    k_wsplit<<<gw, bw>>>(lk, 256, 1);   // W_h

    dim3 gwo(8, 4);
    k_wosplit<<<gwo, bw>>>(w_om);

    k_esplit<<<(Vc * 256) / (256 * 8), 256>>>(embed);

    dim3 g1(ZC / 128, (Bc * Tc) / 128);
    k_xgemm4<<<g1, 256, SMX_TOTAL>>>(x, bias);

    k_lstm5<<<NCTA_L, 512, SMEM_L4>>>();

    k_vu2<<<(Bc * Tc) / 128, 256, SMV_TOTAL>>>(b_om, u_om);

    k_final<<<Bc, 256>>>(w2, b2, out);
}

// round 15
// speedup vs baseline: 1.1315x; 1.1315x over previous
#include <cuda_runtime.h>
#include <cuda_bf16.h>
#include <stdint.h>
#include <math.h>

#define Bc 256
#define Tc 512
#define Dc 256
#define Hc 256
#define Ac 128
#define ZC 1024
#define Vc 50000

#define NCTA_L 128

// ---------------- scratch globals --------------------------------------------
__device__ float g_xz[(size_t)Bc * Tc * ZC];           // fp32 (reverted)
__device__ __nv_bfloat16 g_ohi[(size_t)Bc * Tc * Hc];  // outs, bf16 hi
__device__ __nv_bfloat16 g_olo[(size_t)Bc * Tc * Hc];  // outs, bf16 lo
__device__ float g_vu[Bc * Tc];
__device__ int   g_seqlen[Bc];
__device__ __nv_bfloat16 g_hhi[2][Bc][Hc];
__device__ __nv_bfloat16 g_hlo[2][Bc][Hc];
__device__ unsigned g_bar[16 * 32];
__device__ __nv_bfloat16 g_Bhi[1024 * 256];   // W_x^T hi, [n][k]
__device__ __nv_bfloat16 g_Blo[1024 * 256];
__device__ __nv_bfloat16 g_Whhi[1024 * 256];  // W_h^T hi, [n][k]
__device__ __nv_bfloat16 g_Whlo[1024 * 256];
__device__ __nv_bfloat16 g_WOhi[128 * 256];   // w_omega^T hi, [a][k]
__device__ __nv_bfloat16 g_WOlo[128 * 256];
__device__ __nv_bfloat16 g_Ehi[(size_t)Vc * 256];
__device__ __nv_bfloat16 g_Elo[(size_t)Vc * 256];

typedef unsigned long long u64;

__device__ __forceinline__ float sigm(float x) { return 1.0f / (1.0f + __expf(-x)); }
__device__ __forceinline__ float tanh_f(float x) {
    float ax = fabsf(x);
    float e = __expf(-2.0f * ax);
    float r = (1.0f - e) / (1.0f + e);
    return copysignf(r, x);
}
__device__ __forceinline__ uint32_t smem_u32(const void* p) {
    uint32_t a;
    asm("{ .reg .u64 t; cvta.to.shared.u64 t, %1; cvt.u32.u64 %0, t; }"
        : "=r"(a) : "l"(p));
    return a;
}

// ---------------- mma.sync / cp.async helpers ----------------------------------
__device__ __forceinline__ void ldmx4(uint32_t* r, uint32_t addr) {
    asm volatile("ldmatrix.sync.aligned.m8n8.x4.shared.b16 {%0,%1,%2,%3}, [%4];"
                 : "=r"(r[0]), "=r"(r[1]), "=r"(r[2]), "=r"(r[3]) : "r"(addr));
}
__device__ __forceinline__ void mma16816(float* c, const uint32_t* a,
                                         uint32_t b0, uint32_t b1) {
    asm volatile(
        "mma.sync.aligned.m16n8k16.row.col.f32.bf16.bf16.f32 "
        "{%0,%1,%2,%3}, {%4,%5,%6,%7}, {%8,%9}, {%0,%1,%2,%3};"
        : "+f"(c[0]), "+f"(c[1]), "+f"(c[2]), "+f"(c[3])
        : "r"(a[0]), "r"(a[1]), "r"(a[2]), "r"(a[3]), "r"(b0), "r"(b1));
}
#define CP16(dst, src) \
    asm volatile("cp.async.cg.shared.global [%0], [%1], 16;" \
                 :: "r"(dst), "l"(src) : "memory")
#define CP_COMMIT() asm volatile("cp.async.commit_group;" ::: "memory")
#define CP_WAIT0()  asm volatile("cp.async.wait_group 0;" ::: "memory")

// ---------------- K0: seq_len --------------------------------------------------
__global__ void k_seqlen(const int* __restrict__ x) {
    const int b = blockIdx.x;
    const int tid = threadIdx.x;
    int c = (x[b * Tc + tid] != 0) + (x[b * Tc + 256 + tid] != 0);
    #pragma unroll
    for (int o = 16; o; o >>= 1) c += __shfl_xor_sync(~0u, c, o);
    __shared__ int s[8];
    if ((tid & 31) == 0) s[tid >> 5] = c;
    __syncthreads();
    if (tid == 0) {
        int t = 0;
        #pragma unroll
        for (int i = 0; i < 8; i++) t += s[i];
        g_seqlen[b] = t;
    }
}

__global__ void k_init() {
    if (threadIdx.x < 16 * 32) g_bar[threadIdx.x] = 0u;
}

// ---------------- K0b: W transpose + bf16 hi/lo split --------------------------
__global__ void k_wsplit(const float* __restrict__ lk, int koff, int which) {
    __shared__ float s[32][33];
    const int kt = blockIdx.x * 32;
    const int nt = blockIdx.y * 32;
    const int tx = threadIdx.x;
    const int ty = threadIdx.y;
    #pragma unroll
    for (int i = 0; i < 4; i++) {
        s[ty + 8 * i][tx] = lk[(size_t)(koff + kt + ty + 8 * i) * ZC + nt + tx];
    }
    __syncthreads();
    __nv_bfloat16* dhi = which ? g_Whhi : g_Bhi;
    __nv_bfloat16* dlo = which ? g_Whlo : g_Blo;
    #pragma unroll
    for (int i = 0; i < 4; i++) {
        const int n = ty + 8 * i;
        float v = s[tx][n];
        __nv_bfloat16 h = __float2bfloat16(v);
        float lo = v - __bfloat162float(h);
        dhi[(size_t)(nt + n) * 256 + kt + tx] = h;
        dlo[(size_t)(nt + n) * 256 + kt + tx] = __float2bfloat16(lo);
    }
}

// ---------------- K0b2: w_omega transpose + split -------------------------------
__global__ void k_wosplit(const float* __restrict__ w_om) {
    __shared__ float s[32][33];
    const int kt = blockIdx.x * 32;
    const int at = blockIdx.y * 32;
    const int tx = threadIdx.x;
    const int ty = threadIdx.y;
    #pragma unroll
    for (int i = 0; i < 4; i++) {
        s[ty + 8 * i][tx] = w_om[(size_t)(kt + ty + 8 * i) * Ac + at + tx];
    }
    __syncthreads();
    #pragma unroll
    for (int i = 0; i < 4; i++) {
        const int n = ty + 8 * i;
        float v = s[tx][n];
        __nv_bfloat16 h = __float2bfloat16(v);
        float lo = v - __bfloat162float(h);
        g_WOhi[(size_t)(at + n) * 256 + kt + tx] = h;
        g_WOlo[(size_t)(at + n) * 256 + kt + tx] = __float2bfloat16(lo);
    }
}

// ---------------- K0c: embedding table bf16 hi/lo split ------------------------
__global__ __launch_bounds__(256)
void k_esplit(const float* __restrict__ embed) {
    const size_t base = ((size_t)blockIdx.x * 256 + threadIdx.x) * 8;
    if (base >= (size_t)Vc * 256) return;
    float4 v0 = *(const float4*)(embed + base);
    float4 v1 = *(const float4*)(embed + base + 4);
    __nv_bfloat162 h0 = __floats2bfloat162_rn(v0.x, v0.y);
    __nv_bfloat162 h1 = __floats2bfloat162_rn(v0.z, v0.w);
    __nv_bfloat162 h2 = __floats2bfloat162_rn(v1.x, v1.y);
    __nv_bfloat162 h3 = __floats2bfloat162_rn(v1.z, v1.w);
    __nv_bfloat162 l0 = __floats2bfloat162_rn(v0.x - __bfloat162float(h0.x),
                                              v0.y - __bfloat162float(h0.y));
    __nv_bfloat162 l1 = __floats2bfloat162_rn(v0.z - __bfloat162float(h1.x),
                                              v0.w - __bfloat162float(h1.y));
    __nv_bfloat162 l2 = __floats2bfloat162_rn(v1.x - __bfloat162float(h2.x),
                                              v1.y - __bfloat162float(h2.y));
    __nv_bfloat162 l3 = __floats2bfloat162_rn(v1.z - __bfloat162float(h3.x),
                                              v1.w - __bfloat162float(h3.y));
    uint4 ph;
    ph.x = *(uint32_t*)&h0; ph.y = *(uint32_t*)&h1;
    ph.z = *(uint32_t*)&h2; ph.w = *(uint32_t*)&h3;
    uint4 pl;
    pl.x = *(uint32_t*)&l0; pl.y = *(uint32_t*)&l1;
    pl.z = *(uint32_t*)&l2; pl.w = *(uint32_t*)&l3;
    __stcs((uint4*)&g_Ehi[base], ph);
    __stcs((uint4*)&g_Elo[base], pl);
}

// ---------------- shared GEMM pipeline constants -------------------------------
#define AST2 40
#define X_TOK  0
#define X_BIAS 512
#define X_ARR  10240
#define X_STG  (4 * X_ARR)
#define X_BASE 1024
#define SMX_TOTAL (X_BASE + 2 * X_STG)      // 82944

#define VU_BASE 4096
#define SMV_TOTAL (VU_BASE + 2 * X_STG)     // 86016

extern __shared__ char smx[];

// ---------------- K1: xz GEMM, single-sync cp.async pipeline -------------------
__global__ __launch_bounds__(256, 2)
void k_xgemm4(const int* __restrict__ x, const float* __restrict__ bias) {
    const uint32_t sb = smem_u32(smx);
    const int tid  = threadIdx.x;
    const int wid  = tid >> 5;
    const int lane = tid & 31;
    const int bn = blockIdx.x * 128;
    const int bm = blockIdx.y * 128;

    int*   stok  = (int*)(smx + X_TOK);
    float* sbias = (float*)(smx + X_BIAS);

    if (tid < 128) {
        stok[tid]  = x[bm + tid];
        sbias[tid] = bias[bn + tid];
    }
    __syncthreads();

    const int wm = (wid & 1) * 64;
    const int wn = (wid >> 1) * 32;

    float acc[4][4][4];
    #pragma unroll
    for (int mt = 0; mt < 4; mt++)
        #pragma unroll
        for (int nt = 0; nt < 4; nt++)
            #pragma unroll
            for (int i = 0; i < 4; i++) acc[mt][nt][i] = 0.f;

    const int lrow = tid >> 1;
    const int lk16 = (tid & 1) * 16;
    const size_t asrc = (size_t)stok[lrow] * 256 + lk16;
    const size_t bsrc = (size_t)(bn + lrow) * 256 + lk16;
    const uint32_t ldst = (uint32_t)((lrow * AST2 + lk16) * 2);

    const uint32_t a_comp = (uint32_t)(((wm + (lane & 15)) * AST2 + (lane >> 4) * 8) * 2);
    const uint32_t b_comp = (uint32_t)(((wn + ((lane >> 4) & 1) * 8 + (lane & 7)) * AST2
                                        + ((lane >> 3) & 1) * 8) * 2);

#define X4_ISSUE(CK, STG) do {                                                 \
    const int _kb = (CK) * 32;                                                 \
    const uint32_t _st = sb + X_BASE + (STG) * X_STG + ldst;                   \
    CP16(_st,                 (const char*)&g_Ehi[asrc + _kb]);                \
    CP16(_st + 16,            (const char*)&g_Ehi[asrc + _kb + 8]);            \
    CP16(_st + X_ARR,         (const char*)&g_Elo[asrc + _kb]);                \
    CP16(_st + X_ARR + 16,    (const char*)&g_Elo[asrc + _kb + 8]);            \
    CP16(_st + 2*X_ARR,       (const char*)&g_Bhi[bsrc + _kb]);                \
    CP16(_st + 2*X_ARR + 16,  (const char*)&g_Bhi[bsrc + _kb + 8]);            \
    CP16(_st + 3*X_ARR,       (const char*)&g_Blo[bsrc + _kb]);                \
    CP16(_st + 3*X_ARR + 16,  (const char*)&g_Blo[bsrc + _kb + 8]);            \
    CP_COMMIT();                                                               \
} while (0)

    X4_ISSUE(0, 0);

    for (int ck = 0; ck < 8; ck++) {
        CP_WAIT0();
        __syncthreads();
        if (ck < 7) X4_ISSUE(ck + 1, (ck + 1) & 1);

        const uint32_t stg = sb + X_BASE + (uint32_t)((ck & 1) * X_STG);
        const uint32_t aoff_hi = stg + a_comp;
        const uint32_t aoff_lo = stg + X_ARR + a_comp;
        const uint32_t boff_hi = stg + 2 * X_ARR + b_comp;
        const uint32_t boff_lo = stg + 3 * X_ARR + b_comp;

        #pragma unroll
        for (int ks = 0; ks < 2; ks++) {
            const uint32_t kb = (uint32_t)(ks * 32);
            uint32_t bhi[2][4];
            uint32_t blo[2][4];
            #pragma unroll
            for (int np = 0; np < 2; np++) {
                const uint32_t pb = (uint32_t)(np * 16 * AST2 * 2) + kb;
                ldmx4(bhi[np], boff_hi + pb);
                ldmx4(blo[np], boff_lo + pb);
            }
            #pragma unroll
            for (int mt = 0; mt < 4; mt++) {
                const uint32_t mb = (uint32_t)(mt * 16 * AST2 * 2) + kb;
                uint32_t ahi[4];
                uint32_t alo[4];
                ldmx4(ahi, aoff_hi + mb);
                ldmx4(alo, aoff_lo + mb);
                #pragma unroll
                for (int nt = 0; nt < 4; nt++) {
                    const uint32_t b0 = bhi[nt >> 1][(nt & 1) * 2];
                    const uint32_t b1 = bhi[nt >> 1][(nt & 1) * 2 + 1];
                    const uint32_t c0 = blo[nt >> 1][(nt & 1) * 2];
                    const uint32_t c1 = blo[nt >> 1][(nt & 1) * 2 + 1];
                    mma16816(acc[mt][nt], ahi, b0, b1);
                    mma16816(acc[mt][nt], alo, b0, b1);
                    mma16816(acc[mt][nt], ahi, c0, c1);
                }
            }
        }
    }

    // ---- epilogue: + bias, fp32 stores (reverted) ----
    #pragma unroll
    for (int mt = 0; mt < 4; mt++) {
        const int m0 = bm + wm + mt * 16 + (lane >> 2);
        #pragma unroll
        for (int nt = 0; nt < 4; nt++) {
            const int nl = wn + nt * 8 + (lane & 3) * 2;
            const float b0 = sbias[nl];
            const float b1 = sbias[nl + 1];
            float2 v0;
            float2 v1;
            v0.x = acc[mt][nt][0] + b0;
            v0.y = acc[mt][nt][1] + b1;
            v1.x = acc[mt][nt][2] + b0;
            v1.y = acc[mt][nt][3] + b1;
            __stcs((float2*)&g_xz[(size_t)m0 * ZC + bn + nl], v0);
            __stcs((float2*)&g_xz[(size_t)(m0 + 8) * ZC + bn + nl], v1);
        }
    }
}

// ---------------- K2: LSTM via mma.sync, 4-way K-split -------------------------
// 16 warps = 4 n-quarters (32 cols) x 4 k-groups (64 k).
#define WST 264
#define ZST 136
#define L4_WHI 0
#define L4_WLO 67584
#define L4_HHI 135168
#define L4_HLO 143616
#define L4_ZP  152064
#define SMEM_L4 186880

__global__ __launch_bounds__(512, 1)
void k_lstm5() {
    extern __shared__ char sml[];
    __nv_bfloat16* sWhi = (__nv_bfloat16*)(sml + L4_WHI);
    __nv_bfloat16* sWlo = (__nv_bfloat16*)(sml + L4_WLO);
    __nv_bfloat16* sHhi = (__nv_bfloat16*)(sml + L4_HHI);
    __nv_bfloat16* sHlo = (__nv_bfloat16*)(sml + L4_HLO);
    float* sZp = (float*)(sml + L4_ZP);
    const uint32_t sbase = smem_u32(sml);

    const int tid = threadIdx.x;
    const int g  = blockIdx.x & 7;
    const int bg = blockIdx.x >> 3;
    const int u0 = g * 32;
    const int b0 = bg * 16;
    unsigned* const ctr = &g_bar[bg * 32];

    // W_h slice -> SMEM (once)
    {
        const int n = tid >> 2;
        const int c = tid & 3;
        const int gcol = (n >> 5) * 256 + u0 + (n & 31);
        const size_t src = (size_t)gcol * 256 + c * 64;
        const int dst = n * WST + c * 64;
        #pragma unroll
        for (int i = 0; i < 8; i++) {
            *(uint4*)&sWhi[dst + i * 8] = *(const uint4*)&g_Whhi[src + i * 8];
            *(uint4*)&sWlo[dst + i * 8] = *(const uint4*)&g_Whlo[src + i * 8];
        }
    }

    const int wid  = tid >> 5;
    const int lane = tid & 31;
    const int nh = wid & 3;        // n-quarter (32 cols)
    const int kg = wid >> 2;       // k-group (64 k)
    const int n0 = nh * 32;
    const int k0 = kg * 64;

    const uint32_t a_part = (uint32_t)((lane & 15) * WST + (lane >> 4) * 8) * 2;
    const uint32_t aoff_hi = sbase + L4_HHI + a_part;
    const uint32_t aoff_lo = sbase + L4_HLO + a_part;
    const uint32_t brow = (uint32_t)(n0 + ((lane >> 4) & 1) * 8 + (lane & 7));
    const uint32_t bk   = (uint32_t)(((lane >> 3) & 1) * 8);
    const uint32_t b_part = (brow * WST + bk) * 2;
    const uint32_t boff_hi = sbase + L4_WHI + b_part;
    const uint32_t boff_lo = sbase + L4_WLO + b_part;

    const int gu = lane;
    const int gb = wid;
    float c_reg = 0.f;
    float h_reg = 0.f;
    const int slen = g_seqlen[b0 + gb];
    const size_t xzg = ((size_t)(b0 + gb) * Tc) * ZC + u0 + gu;
    const size_t og  = ((size_t)(b0 + gb) * Tc) * Hc + u0 + gu;
    __nv_bfloat16* const ghh0 = &g_hhi[0][b0 + gb][u0 + gu];
    __nv_bfloat16* const ghh1 = &g_hhi[1][b0 + gb][u0 + gu];
    __nv_bfloat16* const ghl0 = &g_hlo[0][b0 + gb][u0 + gu];
    __nv_bfloat16* const ghl1 = &g_hlo[1][b0 + gb][u0 + gu];

    const int srow = tid >> 5;
    const int skof = lane * 8;
    const __nv_bfloat16* const hshi0 = &g_hhi[0][b0 + srow][skof];
    const __nv_bfloat16* const hshi1 = &g_hhi[1][b0 + srow][skof];
    const __nv_bfloat16* const hslo0 = &g_hlo[0][b0 + srow][skof];
    const __nv_bfloat16* const hslo1 = &g_hlo[1][b0 + srow][skof];
    const int hdst = srow * WST + skof;

    // prefetch xz for t=0
    float xg0 = __ldcs(&g_xz[xzg]);
    float xg1 = __ldcs(&g_xz[xzg + 256]);
    float xg2 = __ldcs(&g_xz[xzg + 512]);
    float xg3 = __ldcs(&g_xz[xzg + 768]);

    for (int t = 0; t < Tc; t++) {
        // stage h(t-1) (pre-split bf16)
        if (t == 0) {
            uint4 z4 = make_uint4(0u, 0u, 0u, 0u);
            *(uint4*)&sHhi[hdst] = z4;
            *(uint4*)&sHlo[hdst] = z4;
        } else {
            const int bsel = t & 1;
            uint4 vh = __ldcg((const uint4*)(bsel ? hshi1 : hshi0));
            uint4 vl = __ldcg((const uint4*)(bsel ? hslo1 : hslo0));
            *(uint4*)&sHhi[hdst] = vh;
            *(uint4*)&sHlo[hdst] = vl;
        }
        __syncthreads();

        // ---- z partial: 16 m x 32 n x 64 k, 3 split terms ----
        float acc[4][4];
        #pragma unroll
        for (int nt = 0; nt < 4; nt++)
            #pragma unroll
            for (int i = 0; i < 4; i++) acc[nt][i] = 0.f;

        #pragma unroll
        for (int ks = 0; ks < 4; ks++) {
            const uint32_t kb = (uint32_t)((k0 + ks * 16) * 2);
            uint32_t ahi[4], alo[4];
            ldmx4(ahi, aoff_hi + kb);
            ldmx4(alo, aoff_lo + kb);
            #pragma unroll
            for (int np = 0; np < 2; np++) {
                const uint32_t pb = (uint32_t)(np * 16 * WST * 2) + kb;
                uint32_t bhi[4], blo[4];
                ldmx4(bhi, boff_hi + pb);
                ldmx4(blo, boff_lo + pb);
                mma16816(acc[2 * np],     ahi, bhi[0], bhi[1]);
                mma16816(acc[2 * np + 1], ahi, bhi[2], bhi[3]);
                mma16816(acc[2 * np],     alo, bhi[0], bhi[1]);
                mma16816(acc[2 * np + 1], alo, bhi[2], bhi[3]);
                mma16816(acc[2 * np],     ahi, blo[0], blo[1]);
                mma16816(acc[2 * np + 1], ahi, blo[2], blo[3]);
            }
        }

        // ---- store partials (4 k-groups x 16 rows) ----
        {
            const int m  = lane >> 2;
            const int cb = (lane & 3) * 2;
            #pragma unroll
            for (int nt = 0; nt < 4; nt++) {
                const int col = n0 + nt * 8 + cb;
                *(float2*)&sZp[(kg * 16 + m) * ZST + col] =
                    make_float2(acc[nt][0], acc[nt][1]);
                *(float2*)&sZp[(kg * 16 + m + 8) * ZST + col] =
                    make_float2(acc[nt][2], acc[nt][3]);
            }
        }
        __syncthreads();

        // ---- gates: reduce 4 k-partials + xz ----
        float zi = xg0;
        float zj = xg1;
        float zf = xg2;
        float zo = xg3;
        #pragma unroll
        for (int p = 0; p < 4; p++) {
            const float* zp = &sZp[(p * 16 + gb) * ZST];
            zi += zp[gu];
            zj += zp[32 + gu];
            zf += zp[64 + gu];
            zo += zp[96 + gu];
        }
        float cn = c_reg * sigm(zf + 1.f) + sigm(zi) * tanh_f(zj);
        float hn = tanh_f(cn) * sigm(zo);
        bool m = (t < slen);
        c_reg = m ? cn : c_reg;
        h_reg = m ? hn : h_reg;

        {
            __nv_bfloat16 hh = __float2bfloat16(h_reg);
            __nv_bfloat16 hl = __float2bfloat16(h_reg - __bfloat162float(hh));
            const int nb = (t + 1) & 1;
            *(nb ? ghh1 : ghh0) = hh;
            *(nb ? ghl1 : ghl0) = hl;
        }

        __threadfence();
        __syncthreads();
        if (tid == 0) atomicAdd(ctr, 1u);

        // hidden under barrier skew: outs store + next xz prefetch
        {
            float o = m ? hn : 0.f;
            __nv_bfloat16 oh = __float2bfloat16(o);
            __nv_bfloat16 ol = __float2bfloat16(o - __bfloat162float(oh));
            g_ohi[og + (size_t)t * Hc] = oh;
            g_olo[og + (size_t)t * Hc] = ol;
        }
        if (t + 1 < Tc) {
            const size_t xb = xzg + (size_t)(t + 1) * ZC;
            xg0 = __ldcs(&g_xz[xb]);
            xg1 = __ldcs(&g_xz[xb + 256]);
            xg2 = __ldcs(&g_xz[xb + 512]);
            xg3 = __ldcs(&g_xz[xb + 768]);
        }

        if (tid == 0) {
            const unsigned target = (unsigned)(t + 1) * 8u;
            unsigned v;
            do {
                asm volatile("ld.global.acquire.gpu.u32 %0, [%1];"
                             : "=r"(v) : "l"(ctr) : "memory");
            } while (v < target);
        }
        __syncthreads();
    }
}

// ---------------- K3: attention scores via HMMA (single-sync) ------------------
__global__ __launch_bounds__(256, 2)
void k_vu2(const float* __restrict__ b_om, const float* __restrict__ u_om) {
    const uint32_t sb = smem_u32(smx);
    const int tid  = threadIdx.x;
    const int wid  = tid >> 5;
    const int lane = tid & 31;
    const int bm = blockIdx.x * 128;

    float* sbom = (float*)(smx + 0);
    float* suom = (float*)(smx + 512);
    float* sred = (float*)(smx + 1024);

    if (tid < 128) {
        sbom[tid] = b_om[tid];
        suom[tid] = u_om[tid];
    }
    __syncthreads();

    const int wm = (wid & 1) * 64;
    const int wn = (wid >> 1) * 32;

    float acc[4][4][4];
    #pragma unroll
    for (int mt = 0; mt < 4; mt++)
        #pragma unroll
        for (int nt = 0; nt < 4; nt++)
            #pragma unroll
            for (int i = 0; i < 4; i++) acc[mt][nt][i] = 0.f;

    const int lrow = tid >> 1;
    const int lk16 = (tid & 1) * 16;
    const size_t asrc = (size_t)(bm + lrow) * 256 + lk16;
    const size_t bsrc = (size_t)lrow * 256 + lk16;
    const uint32_t ldst = (uint32_t)((lrow * AST2 + lk16) * 2);

    const uint32_t a_comp = (uint32_t)(((wm + (lane & 15)) * AST2 + (lane >> 4) * 8) * 2);
    const uint32_t b_comp = (uint32_t)(((wn + ((lane >> 4) & 1) * 8 + (lane & 7)) * AST2
                                        + ((lane >> 3) & 1) * 8) * 2);

#define VU_ISSUE(CK, STG) do {                                                 \
    const int _kb = (CK) * 32;                                                 \
    const uint32_t _st = sb + VU_BASE + (STG) * X_STG + ldst;                  \
    CP16(_st,                 (const char*)&g_ohi[asrc + _kb]);                \
    CP16(_st + 16,            (const char*)&g_ohi[asrc + _kb + 8]);            \
    CP16(_st + X_ARR,         (const char*)&g_olo[asrc + _kb]);                \
    CP16(_st + X_ARR + 16,    (const char*)&g_olo[asrc + _kb + 8]);            \
    CP16(_st + 2*X_ARR,       (const char*)&g_WOhi[bsrc + _kb]);               \
    CP16(_st + 2*X_ARR + 16,  (const char*)&g_WOhi[bsrc + _kb + 8]);           \
    CP16(_st + 3*X_ARR,       (const char*)&g_WOlo[bsrc + _kb]);               \
    CP16(_st + 3*X_ARR + 16,  (const char*)&g_WOlo[bsrc + _kb + 8]);           \
    CP_COMMIT();                                                               \
} while (0)

    VU_ISSUE(0, 0);

    for (int ck = 0; ck < 8; ck++) {
        CP_WAIT0();
        __syncthreads();
        if (ck < 7) VU_ISSUE(ck + 1, (ck + 1) & 1);

        const uint32_t stg = sb + VU_BASE + (uint32_t)((ck & 1) * X_STG);
        const uint32_t aoff_hi = stg + a_comp;
        const uint32_t aoff_lo = stg + X_ARR + a_comp;
        const uint32_t boff_hi = stg + 2 * X_ARR + b_comp;
        const uint32_t boff_lo = stg + 3 * X_ARR + b_comp;

        #pragma unroll
        for (int ks = 0; ks < 2; ks++) {
            const uint32_t kb = (uint32_t)(ks * 32);
            uint32_t bhi[2][4];
            uint32_t blo[2][4];
            #pragma unroll
            for (int np = 0; np < 2; np++) {
                const uint32_t pb = (uint32_t)(np * 16 * AST2 * 2) + kb;
                ldmx4(bhi[np], boff_hi + pb);
                ldmx4(blo[np], boff_lo + pb);
            }
            #pragma unroll
            for (int mt = 0; mt < 4; mt++) {
                const uint32_t mb = (uint32_t)(mt * 16 * AST2 * 2) + kb;
                uint32_t ahi[4];
                uint32_t alo[4];
                ldmx4(ahi, aoff_hi + mb);
                ldmx4(alo, aoff_lo + mb);
                #pragma unroll
                for (int nt = 0; nt < 4; nt++) {
                    const uint32_t b0 = bhi[nt >> 1][(nt & 1) * 2];
                    const uint32_t b1 = bhi[nt >> 1][(nt & 1) * 2 + 1];
                    const uint32_t c0 = blo[nt >> 1][(nt & 1) * 2];
                    const uint32_t c1 = blo[nt >> 1][(nt & 1) * 2 + 1];
                    mma16816(acc[mt][nt], ahi, b0, b1);
                    mma16816(acc[mt][nt], alo, b0, b1);
                    mma16816(acc[mt][nt], ahi, c0, c1);
                }
            }
        }
    }
    __syncthreads();

    // ---- epilogue: tanh(+b)*u, row-sum over n=128 ----
    #pragma unroll
    for (int mt = 0; mt < 4; mt++) {
        float rsum[2];
        rsum[0] = 0.f;
        rsum[1] = 0.f;
        #pragma unroll
        for (int nt = 0; nt < 4; nt++) {
            #pragma unroll
            for (int i = 0; i < 4; i++) {
                const int col = wn + nt * 8 + (lane & 3) * 2 + (i & 1);
                float v = tanh_f(acc[mt][nt][i] + sbom[col]) * suom[col];
                rsum[i >> 1] += v;
            }
        }
        #pragma unroll
        for (int hf = 0; hf < 2; hf++) {
            float r = rsum[hf];
            r += __shfl_xor_sync(~0u, r, 1);
            r += __shfl_xor_sync(~0u, r, 2);
            if ((lane & 3) == 0) {
                const int row = wm + mt * 16 + (lane >> 2) + hf * 8;
                sred[row * 4 + (wid >> 1)] = r;
            }
        }
    }
    __syncthreads();
    if (tid < 128) {
        g_vu[bm + tid] = sred[tid * 4] + sred[tid * 4 + 1]
                       + sred[tid * 4 + 2] + sred[tid * 4 + 3];
    }
}

// ---------------- 512-thread block reductions -----------------------------------
__device__ __forceinline__ float bsum512(float v, float* sr, int tid) {
    #pragma unroll
    for (int o = 16; o; o >>= 1) v += __shfl_xor_sync(~0u, v, o);
    __syncthreads();               // protect sr from prior use
    if ((tid & 31) == 0) sr[tid >> 5] = v;
    __syncthreads();
    if (tid < 32) {
        float xx = (tid < 16) ? sr[tid] : 0.f;
        #pragma unroll
        for (int o = 8; o; o >>= 1) xx += __shfl_xor_sync(~0u, xx, o);
        if (tid == 0) sr[0] = xx;
    }
    __syncthreads();
    return sr[0];
}
__device__ __forceinline__ float bmax512(float v, float* sr, int tid) {
    #pragma unroll
    for (int o = 16; o; o >>= 1) v = fmaxf(v, __shfl_xor_sync(~0u, v, o));
    __syncthreads();
    if ((tid & 31) == 0) sr[tid >> 5] = v;
    __syncthreads();
    if (tid < 32) {
        float xx = (tid < 16) ? sr[tid] : -INFINITY;
        #pragma unroll
        for (int o = 8; o; o >>= 1) xx = fmaxf(xx, __shfl_xor_sync(~0u, xx, o));
        if (tid == 0) sr[0] = xx;
    }
    __syncthreads();
    return sr[0];
}

// ---------------- K4: softmax over T, weighted sum, head (512 threads) ---------
__global__ __launch_bounds__(512)
void k_final(const float* __restrict__ w2, const float* __restrict__ b2,
             float* __restrict__ out) {
    __shared__ float sa[Tc];
    __shared__ float sr[16];
    __shared__ float sacc[2][256];

    const int b = blockIdx.x;
    const int tid = threadIdx.x;

    const float v = g_vu[b * Tc + tid];
    const float m = bmax512(v, sr, tid);
    const float e = expf(v - m);
    sa[tid] = e;
    const float Z = bsum512(e, sr, tid);   // also orders sa writes
    const float Zinv = 1.0f / Z;

    // weighted sum: unit u over t-half
    const int u = tid & 255;
    const int half = tid >> 8;
    const __nv_bfloat16* oph = g_ohi + (size_t)b * Tc * Hc + u;
    const __nv_bfloat16* opl = g_olo + (size_t)b * Tc * Hc + u;
    float a[4];
    #pragma unroll
    for (int i = 0; i < 4; i++) a[i] = 0.f;
    const int t0 = half * 256;
    for (int t = t0; t < t0 + 256; t += 4) {
        #pragma unroll
        for (int i = 0; i < 4; i++) {
            const size_t off = (size_t)(t + i) * Hc;
            float vv = __bfloat162float(__ldcg(&oph[off]))
                     + __bfloat162float(__ldcg(&opl[off]));
            a[i] = fmaf(vv, sa[t + i], a[i]);
        }
    }
    sacc[half][u] = (a[0] + a[1]) + (a[2] + a[3]);
    __syncthreads();

    float acc = 0.f;
    float w0 = 0.f;
    float w1 = 0.f;
    if (tid < 256) {
        acc = (sacc[0][tid] + sacc[1][tid]) * Zinv;
        w0 = w2[tid * 2];
        w1 = w2[tid * 2 + 1];
    }
    const float l0 = bsum512(acc * w0, sr, tid);
    const float l1 = bsum512(acc * w1, sr, tid);

    if (tid == 0) {
        float aa0 = l0 + b2[0];
        float aa1 = l1 + b2[1];
        float mm = fmaxf(aa0, aa1);
        float x0 = expf(aa0 - mm);
        float x1 = expf(aa1 - mm);
        float s = 1.0f / (x0 + x1);
        out[b * 2 + 0] = x0 * s;
        out[b * 2 + 1] = x1 * s;
    }
}

// ---------------- launcher -------------------------------------------------------
extern "C" void kernel_launch(void* const* d_in, const int* in_sizes, int n_in,
                              void* d_out, int out_size) {
    const int*   x     = (const int*)  d_in[0];
    const float* embed = (const float*)d_in[1];
    const float* lk    = (const float*)d_in[2];
    const float* bias  = (const float*)d_in[3];
    const float* w_om  = (const float*)d_in[4];
    const float* b_om  = (const float*)d_in[5];
    const float* u_om  = (const float*)d_in[6];
    const float* w2    = (const float*)d_in[7];
    const float* b2    = (const float*)d_in[8];
    float* out = (float*)d_out;

    cudaFuncSetAttribute(k_xgemm4, cudaFuncAttributeMaxDynamicSharedMemorySize,
                         SMX_TOTAL);
    cudaFuncSetAttribute(k_vu2, cudaFuncAttributeMaxDynamicSharedMemorySize,
                         SMV_TOTAL);
    cudaFuncSetAttribute(k_lstm5, cudaFuncAttributeMaxDynamicSharedMemorySize,
                         SMEM_L4);

    k_seqlen<<<Bc, 256>>>(x);
    k_init<<<1, 512>>>();

    dim3 gw(8, 32);
    dim3 bw(32, 8);
    k_wsplit<<<gw, bw>>>(lk, 0, 0);     // W_x
    k_wsplit<<<gw, bw>>>(lk, 256, 1);   // W_h

    dim3 gwo(8, 4);
    k_wosplit<<<gwo, bw>>>(w_om);

    k_esplit<<<(Vc * 256) / (256 * 8), 256>>>(embed);

    dim3 g1(ZC / 128, (Bc * Tc) / 128);
    k_xgemm4<<<g1, 256, SMX_TOTAL>>>(x, bias);

    k_lstm5<<<NCTA_L, 512, SMEM_L4>>>();

    k_vu2<<<(Bc * Tc) / 128, 256, SMV_TOTAL>>>(b_om, u_om);

    k_final<<<Bc, 512>>>(w2, b2, out);
}